// round 1
// baseline (speedup 1.0000x reference)
#include <cuda_runtime.h>
#include <math.h>

#define BB 16
#define NN 16384
#define TOTAL (BB * NN)
#define NCHUNK (NN / 32)

// Scratch: per-sample 7 taps + x (two float4) and zc (int). 9 MB total -> L2 resident.
__device__ float4 g_cA[TOTAL];
__device__ float4 g_cB[TOTAL];
__device__ int    g_zc[TOTAL];

// ---------------------------------------------------------------------------
// Pass 1: fully parallel coefficient computation.
//   g = 0.99*lb0, p = lb1, b0 = g(1-p), a1 = g*p
//   f0c = f0 - a1/(b0+a1+1e-7);  zc = floor(f0c)-2;  alpha = f0c - zc in [2,3)
//   Lagrange-5 weights w_j = (prod_{k!=j} (alpha-k)) * c_j,
//   c = {-1/120, 1/24, -1/12, 1/12, -1/24, 1/120}  (prefix/suffix products,
//   no division by (alpha-j) so integer alpha is exact).
//   blk[0]=b0*w0; blk[j]=b0*w[j]+a1*w[j-1] (1..5); blk[6]=a1*w5.
// ---------------------------------------------------------------------------
__global__ void __launch_bounds__(256)
coef_kernel(const float* __restrict__ f0,
            const float* __restrict__ x,
            const float* __restrict__ lb)
{
    int i = blockIdx.x * blockDim.x + threadIdx.x;
    if (i >= TOTAL) return;

    float2 gp = reinterpret_cast<const float2*>(lb)[i];
    float g  = 0.99f * gp.x;
    float p  = gp.y;
    float b0 = g * (1.0f - p);
    float a1 = g * p;
    float f0c = f0[i] - a1 / (b0 + a1 + 1e-7f);

    int   zc    = (int)floorf(f0c) - 2;
    float alpha = f0c - (float)zc;          // in [2, 3)

    float u0 = alpha;
    float u1 = alpha - 1.0f;
    float u2 = alpha - 2.0f;
    float u3 = alpha - 3.0f;
    float u4 = alpha - 4.0f;
    float u5 = alpha - 5.0f;

    float pre1 = u0;
    float pre2 = pre1 * u1;
    float pre3 = pre2 * u2;
    float pre4 = pre3 * u3;
    float pre5 = pre4 * u4;
    float suf4 = u5;
    float suf3 = suf4 * u4;
    float suf2 = suf3 * u3;
    float suf1 = suf2 * u2;
    float suf0 = suf1 * u1;

    float w0 = suf0        * (-1.0f / 120.0f);
    float w1 = pre1 * suf1 * ( 1.0f /  24.0f);
    float w2 = pre2 * suf2 * (-1.0f /  12.0f);
    float w3 = pre3 * suf3 * ( 1.0f /  12.0f);
    float w4 = pre4 * suf4 * (-1.0f /  24.0f);
    float w5 = pre5        * ( 1.0f / 120.0f);

    g_cA[i] = make_float4(b0 * w0,
                          fmaf(b0, w1, a1 * w0),
                          fmaf(b0, w2, a1 * w1),
                          fmaf(b0, w3, a1 * w2));
    g_cB[i] = make_float4(fmaf(b0, w4, a1 * w3),
                          fmaf(b0, w5, a1 * w4),
                          a1 * w5,
                          x[i]);
    g_zc[i] = zc;
}

// ---------------------------------------------------------------------------
// Pass 2: sequential recurrence, one warp per batch row.
//   y[n] = x[n] + sum_{j=0..6} blk[j] * y[n - zc - j],  delays in [37, 103].
//   Min delay 37 > 32  =>  a chunk of 32 samples is internally independent.
//   Ring buffer of 256 recent y values in SMEM; write slots and read slots of
//   one chunk are disjoint mod 256, so a single __syncwarp per chunk orders
//   writes(c-1) before reads(c).
//   Coefficient loads prefetched 2 chunks ahead (L2-resident after pass 1).
// ---------------------------------------------------------------------------
__global__ void __launch_bounds__(32, 1)
lpc_kernel(float* __restrict__ out)
{
    __shared__ float y_s[256];

    const int b    = blockIdx.x;
    const int lane = threadIdx.x;
    const float4* __restrict__ cA  = g_cA + b * NN;
    const float4* __restrict__ cB  = g_cB + b * NN;
    const int*    __restrict__ zca = g_zc + b * NN;
    float* __restrict__ outr = out + b * NN;

    // pipeline stages: chunk c (stage 0) and c+1 (stage 1) resident in regs
    float4 A0 = cA[lane];      float4 B0 = cB[lane];      int z0 = zca[lane];
    float4 A1 = cA[32 + lane]; float4 B1 = cB[32 + lane]; int z1 = zca[32 + lane];

    for (int c = 0; c < NCHUNK; c++) {
        // prefetch chunk c+2 (fire-and-forget, consumed 2 iterations later)
        float4 A2 = make_float4(0.f, 0.f, 0.f, 0.f);
        float4 B2 = A2;
        int    z2 = 64;
        if (c + 2 < NCHUNK) {
            int m = (c + 2) * 32 + lane;
            A2 = cA[m]; B2 = cB[m]; z2 = zca[m];
        }

        const int n    = c * 32 + lane;
        const int base = n - z0;      // delays: base-j for j=0..6, all <= n-37

        float y0 = (base     >= 0) ? y_s[(base    ) & 255] : 0.0f;
        float y1 = (base - 1 >= 0) ? y_s[(base - 1) & 255] : 0.0f;
        float y2 = (base - 2 >= 0) ? y_s[(base - 2) & 255] : 0.0f;
        float y3 = (base - 3 >= 0) ? y_s[(base - 3) & 255] : 0.0f;
        float y4 = (base - 4 >= 0) ? y_s[(base - 4) & 255] : 0.0f;
        float y5 = (base - 5 >= 0) ? y_s[(base - 5) & 255] : 0.0f;
        float y6 = (base - 6 >= 0) ? y_s[(base - 6) & 255] : 0.0f;

        // balanced FMA tree (depth ~3) instead of a 7-long serial chain
        float s0 = fmaf(A0.x, y0, B0.w);       // x[n] + blk0*y0
        float s1 = fmaf(A0.z, y2, A0.y * y1);
        float s2 = fmaf(B0.x, y4, A0.w * y3);
        float s3 = fmaf(B0.z, y6, B0.y * y5);
        float acc = (s0 + s1) + (s2 + s3);

        y_s[n & 255] = acc;   // write slot disjoint from this chunk's read slots
        outr[n] = acc;        // fire-and-forget STG
        __syncwarp();

        A0 = A1; B0 = B1; z0 = z1;
        A1 = A2; B1 = B2; z1 = z2;
    }
}

// ---------------------------------------------------------------------------
// Inputs (metadata order): f0 [B,N] f32, x [B,N] f32, l_b [B,N,2] f32, K int32
// Output: y [B,N] f32
// ---------------------------------------------------------------------------
extern "C" void kernel_launch(void* const* d_in, const int* in_sizes, int n_in,
                              void* d_out, int out_size)
{
    const float* f0 = (const float*)d_in[0];
    const float* x  = (const float*)d_in[1];
    const float* lb = (const float*)d_in[2];
    float* out = (float*)d_out;

    coef_kernel<<<TOTAL / 256, 256>>>(f0, x, lb);
    lpc_kernel<<<BB, 32>>>(out);
}

// round 3
// speedup vs baseline: 1.7154x; 1.7154x over previous
#include <cuda_runtime.h>
#include <math.h>

#define BB 16
#define NN 16384
#define TOTAL (BB * NN)
#define NCHUNK (NN / 32)

// Scratch: per-sample 7 taps + x (two float4) and bm6 = n - zc - 6 (int).
__device__ float4 g_cA[TOTAL];
__device__ float4 g_cB[TOTAL];
__device__ int    g_bm6[TOTAL];

// ---------------------------------------------------------------------------
// Pass 1: fully parallel coefficient computation.
//   blk[0]=b0*w0; blk[j]=b0*w[j]+a1*w[j-1] (j=1..5); blk[6]=a1*w5;  B.w=x[n].
//   Stores bm6 = n - zc - 6 (start of the 7-tap read window).
// ---------------------------------------------------------------------------
__global__ void __launch_bounds__(256)
coef_kernel(const float* __restrict__ f0,
            const float* __restrict__ x,
            const float* __restrict__ lb)
{
    int i = blockIdx.x * blockDim.x + threadIdx.x;
    if (i >= TOTAL) return;
    int n = i & (NN - 1);

    float2 gp = reinterpret_cast<const float2*>(lb)[i];
    float g  = 0.99f * gp.x;
    float p  = gp.y;
    float b0 = g * (1.0f - p);
    float a1 = g * p;
    float f0c = f0[i] - a1 / (b0 + a1 + 1e-7f);

    int   zc    = (int)floorf(f0c) - 2;
    float alpha = f0c - (float)zc;          // in [2, 3)

    float u0 = alpha;
    float u1 = alpha - 1.0f;
    float u2 = alpha - 2.0f;
    float u3 = alpha - 3.0f;
    float u4 = alpha - 4.0f;
    float u5 = alpha - 5.0f;

    float pre1 = u0;
    float pre2 = pre1 * u1;
    float pre3 = pre2 * u2;
    float pre4 = pre3 * u3;
    float pre5 = pre4 * u4;
    float suf4 = u5;
    float suf3 = suf4 * u4;
    float suf2 = suf3 * u3;
    float suf1 = suf2 * u2;
    float suf0 = suf1 * u1;

    float w0 = suf0        * (-1.0f / 120.0f);
    float w1 = pre1 * suf1 * ( 1.0f /  24.0f);
    float w2 = pre2 * suf2 * (-1.0f /  12.0f);
    float w3 = pre3 * suf3 * ( 1.0f /  12.0f);
    float w4 = pre4 * suf4 * (-1.0f /  24.0f);
    float w5 = pre5        * ( 1.0f / 120.0f);

    g_cA[i] = make_float4(b0 * w0,
                          fmaf(b0, w1, a1 * w0),
                          fmaf(b0, w2, a1 * w1),
                          fmaf(b0, w3, a1 * w2));
    g_cB[i] = make_float4(fmaf(b0, w4, a1 * w3),
                          fmaf(b0, w5, a1 * w4),
                          a1 * w5,
                          x[i]);
    g_bm6[i] = n - zc - 6;
}

// ---------------------------------------------------------------------------
// Pass 2: sequential recurrence, one warp per batch row.
//   y[n] = x[n] + sum_{j=0..6} blk[j]*y[n-zc-j],  delays in [37, 103].
//   SMEM ring of 256 + 7-slot mirror (slot 256+u == slot u) so the read
//   window [lo, lo+6] never wraps -> branchless LDS with immediate offsets.
//   Pre-zeroed ring makes negative-index reads (n < 104 only) land on slots
//   [153,255] which are still zero at that time -> zero initial state free.
//   Write slot inside an 8-chunk group is statically lane + (c&7)*32; mirror
//   store only on chunks c % 8 == 0 (predicated, lanes 0..6).
// ---------------------------------------------------------------------------
struct Chunk { float4 A, B; int bm6; };

__device__ __forceinline__ void load_group(const float4* __restrict__ cA,
                                           const float4* __restrict__ cB,
                                           const int*    __restrict__ cb,
                                           int cg, int lane, Chunk* N)
{
#pragma unroll
    for (int k = 0; k < 4; k++) {
        int ci = cg + k;
        if (ci > NCHUNK - 1) ci = NCHUNK - 1;   // tail clamp (values unused)
        int idx = ci * 32 + lane;
        N[k].A = cA[idx];
        N[k].B = cB[idx];
        N[k].bm6 = cb[idx];
    }
}

template<bool MIRROR>   // MIRROR: group starts at chunk c % 8 == 0
__device__ __forceinline__ void proc_group(const Chunk* C, float* __restrict__ y_s,
                                           int lane, bool lane_lt7,
                                           int wbase,          // 0 or 128 (slots)
                                           float* __restrict__ op)
{
#pragma unroll
    for (int k = 0; k < 4; k++) {
        const Chunk& ck = C[k];
        const int lo = ck.bm6 & 255;
        // window [lo, lo+6] <= 262; mirror slots cover the tail
        float v6 = y_s[lo    ];
        float v5 = y_s[lo + 1];
        float v4 = y_s[lo + 2];
        float v3 = y_s[lo + 3];
        float v2 = y_s[lo + 4];
        float v1 = y_s[lo + 5];
        float v0 = y_s[lo + 6];

        float t0 = fmaf(ck.A.x, v0, ck.B.w);     // x[n] + blk0*v0
        float t1 = fmaf(ck.A.z, v2, ck.A.y * v1);
        float t2 = fmaf(ck.B.x, v4, ck.A.w * v3);
        float t3 = fmaf(ck.B.z, v6, ck.B.y * v5);
        float acc = (t0 + t1) + (t2 + t3);

        y_s[wbase + k * 32 + lane] = acc;
        if (MIRROR && k == 0 && lane_lt7) y_s[256 + lane] = acc;
        op[k * 32] = acc;
        __syncwarp();
    }
}

__global__ void __launch_bounds__(32, 1)
lpc_kernel(float* __restrict__ out)
{
    __shared__ float y_s[264];

    const int b    = blockIdx.x;
    const int lane = threadIdx.x;
    const bool lane_lt7 = lane < 7;
    const float4* __restrict__ cA = g_cA  + b * NN;
    const float4* __restrict__ cB = g_cB  + b * NN;
    const int*    __restrict__ cb = g_bm6 + b * NN;
    float* __restrict__ outr = out + b * NN + lane;

#pragma unroll
    for (int k = 0; k < 8; k++) y_s[lane + 32 * k] = 0.0f;
    if (lane < 8) y_s[256 + lane] = 0.0f;
    __syncwarp();

    Chunk C[4], D[4];
    load_group(cA, cB, cb, 0, lane, C);

    for (int cg = 0; cg < NCHUNK; cg += 8) {
        load_group(cA, cB, cb, cg + 4, lane, D);      // prefetch chunks cg+4..7
        proc_group<true >(C, y_s, lane, lane_lt7,   0, outr + cg * 32);
        load_group(cA, cB, cb, cg + 8, lane, C);      // prefetch next group
        proc_group<false>(D, y_s, lane, lane_lt7, 128, outr + cg * 32 + 128);
    }
}

// ---------------------------------------------------------------------------
// Inputs (metadata order): f0 [B,N] f32, x [B,N] f32, l_b [B,N,2] f32, K int32
// Output: y [B,N] f32
// ---------------------------------------------------------------------------
extern "C" void kernel_launch(void* const* d_in, const int* in_sizes, int n_in,
                              void* d_out, int out_size)
{
    const float* f0 = (const float*)d_in[0];
    const float* x  = (const float*)d_in[1];
    const float* lb = (const float*)d_in[2];
    float* out = (float*)d_out;

    coef_kernel<<<TOTAL / 256, 256>>>(f0, x, lb);
    lpc_kernel<<<BB, 32>>>(out);
}

// round 5
// speedup vs baseline: 2.7242x; 1.5881x over previous
#include <cuda_runtime.h>
#include <math.h>

#define BB 16
#define NN 16384
#define TOTAL (BB * NN)
#define NCHUNK (NN / 32)        // 512
#define NGROUP (NCHUNK / 4)     // 128 groups of 4 chunks

// Scratch (padded so tail prefetches stay in-bounds; pad values never used).
__device__ float4 g_cA[TOTAL + 512];
__device__ float4 g_cB[TOTAL + 512];
__device__ int    g_lo[TOTAL + 512];

// ---------------------------------------------------------------------------
// Pass 1: fully parallel coefficient computation.
//   blk[0]=b0*w0; blk[j]=b0*w[j]+a1*w[j-1] (j=1..5); blk[6]=a1*w5;  B.w=x[n].
//   Stores lo = (n - zc - 6) & 255  (ring slot of the 7-tap window start).
// ---------------------------------------------------------------------------
__global__ void __launch_bounds__(256)
coef_kernel(const float* __restrict__ f0,
            const float* __restrict__ x,
            const float* __restrict__ lb)
{
    int i = blockIdx.x * blockDim.x + threadIdx.x;
    if (i >= TOTAL) return;
    int n = i & (NN - 1);

    float2 gp = reinterpret_cast<const float2*>(lb)[i];
    float g  = 0.99f * gp.x;
    float p  = gp.y;
    float b0 = g * (1.0f - p);
    float a1 = g * p;
    float f0c = f0[i] - a1 / (b0 + a1 + 1e-7f);

    int   zc    = (int)floorf(f0c) - 2;
    float alpha = f0c - (float)zc;          // in [2, 3)

    float u0 = alpha;
    float u1 = alpha - 1.0f;
    float u2 = alpha - 2.0f;
    float u3 = alpha - 3.0f;
    float u4 = alpha - 4.0f;
    float u5 = alpha - 5.0f;

    float pre1 = u0;
    float pre2 = pre1 * u1;
    float pre3 = pre2 * u2;
    float pre4 = pre3 * u3;
    float pre5 = pre4 * u4;
    float suf4 = u5;
    float suf3 = suf4 * u4;
    float suf2 = suf3 * u3;
    float suf1 = suf2 * u2;
    float suf0 = suf1 * u1;

    float w0 = suf0        * (-1.0f / 120.0f);
    float w1 = pre1 * suf1 * ( 1.0f /  24.0f);
    float w2 = pre2 * suf2 * (-1.0f /  12.0f);
    float w3 = pre3 * suf3 * ( 1.0f /  12.0f);
    float w4 = pre4 * suf4 * (-1.0f /  24.0f);
    float w5 = pre5        * ( 1.0f / 120.0f);

    g_cA[i] = make_float4(b0 * w0,
                          fmaf(b0, w1, a1 * w0),
                          fmaf(b0, w2, a1 * w1),
                          fmaf(b0, w3, a1 * w2));
    g_cB[i] = make_float4(fmaf(b0, w4, a1 * w3),
                          fmaf(b0, w5, a1 * w4),
                          a1 * w5,
                          x[i]);
    g_lo[i] = (n - zc - 6) & 255;
}

// ---------------------------------------------------------------------------
// cp.async helpers
// ---------------------------------------------------------------------------
__device__ __forceinline__ void cp16(void* dst, const void* src) {
    unsigned int d = (unsigned int)__cvta_generic_to_shared(dst);
    asm volatile("cp.async.ca.shared.global [%0], [%1], 16;" :: "r"(d), "l"(src));
}
__device__ __forceinline__ void cp4(void* dst, const void* src) {
    unsigned int d = (unsigned int)__cvta_generic_to_shared(dst);
    asm volatile("cp.async.ca.shared.global [%0], [%1], 4;" :: "r"(d), "l"(src));
}
__device__ __forceinline__ void cp_commit() {
    asm volatile("cp.async.commit_group;");
}
__device__ __forceinline__ void cp_wait2() {
    asm volatile("cp.async.wait_group 2;");
}

// ---------------------------------------------------------------------------
// Pass 2: sequential recurrence, one warp per batch row.
//   y[n] = x[n] + sum_{j=0..6} blk[j]*y[n-zc-j],  delays in [37, 103].
//   - SMEM ring (256 + 7 mirror): branchless 7-tap window with immediate
//     offsets; one __syncwarp per chunk orders STS(c-1) before LDS(c)
//     (required: sm_103a STS has no store-forward; round-4 removal failed).
//   - pre-zeroed ring + wrap mapping implements the zero initial state.
//   - coefficients stream through a 16-stage SMEM buffer via cp.async,
//     committed one 4-chunk group at a time, wait_group 2 => ~8-chunk lead.
// ---------------------------------------------------------------------------
struct SmemCoef {
    float4 A[16][32];
    float4 B[16][32];
    int    I[16][32];
};

__device__ __forceinline__ void prefetch_chunk(SmemCoef* s, int st, int c, int lane,
                                               const float4* cA, const float4* cB,
                                               const int* cI)
{
    int idx = c * 32 + lane;
    cp16(&s->A[st][lane], cA + idx);
    cp16(&s->B[st][lane], cB + idx);
    cp4 (&s->I[st][lane], cI + idx);
}

template<bool MIRROR>
__device__ __forceinline__ void proc_chunk(SmemCoef* s, int st, int wslot,
                                           int lane, bool lane_lt7,
                                           float* ring, float* op)
{
    const float4 A  = s->A[st][lane];
    const float4 B  = s->B[st][lane];
    const int    lo = s->I[st][lane];

    const float* w = ring + lo;              // window [lo, lo+6], never wraps
    float v6 = w[0];
    float v5 = w[1];
    float v4 = w[2];
    float v3 = w[3];
    float v2 = w[4];
    float v1 = w[5];
    float v0 = w[6];

    float t0 = fmaf(A.x, v0, B.w);           // x[n] + blk0*v0
    float t1 = fmaf(A.z, v2, A.y * v1);
    float t2 = fmaf(B.x, v4, A.w * v3);
    float t3 = fmaf(B.z, v6, B.y * v5);
    float acc = (t0 + t1) + (t2 + t3);

    ring[wslot + lane] = acc;
    if (MIRROR && lane_lt7) ring[256 + lane] = acc;
    *op = acc;
    __syncwarp();                            // STS(c) visible before LDS(c+1)
}

// One phase = consume 4 chunks (group grp, stages STB..STB+3) and prefetch
// group grp+3 into stages NSTB..NSTB+3 (freed in the previous phase).
template<int STB, int WB, bool MIR, int NSTB>
__device__ __forceinline__ void phase(SmemCoef* s, int grp, int lane, bool lane_lt7,
                                      float* ring, float* op,
                                      const float4* cA, const float4* cB, const int* cI)
{
    cp_wait2();                               // group grp's data is resident
    const int pc0 = (grp + 3) * 4;            // chunks to prefetch
    float* opg = op + grp * 128;
#pragma unroll
    for (int k = 0; k < 4; k++) {
        proc_chunk<(MIR)>(s, STB + k, WB + k * 32,
                          lane, (k == 0) ? lane_lt7 : false, ring, opg + k * 32);
        prefetch_chunk(s, NSTB + k, pc0 + k, lane, cA, cB, cI);
    }
    cp_commit();
}

__global__ void __launch_bounds__(32, 1)
lpc_kernel(float* __restrict__ out)
{
    __shared__ SmemCoef sc;
    __shared__ float ring[264];

    const int b    = blockIdx.x;
    const int lane = threadIdx.x;
    const bool lane_lt7 = lane < 7;
    const float4* __restrict__ cA = g_cA + b * NN;
    const float4* __restrict__ cB = g_cB + b * NN;
    const int*    __restrict__ cI = g_lo + b * NN;
    float* __restrict__ op = out + b * NN + lane;

#pragma unroll
    for (int k = 0; k < 8; k++) ring[lane + 32 * k] = 0.0f;
    if (lane < 8) ring[256 + lane] = 0.0f;

    // prime pipeline: groups 0,1,2 -> stages 0-11
#pragma unroll
    for (int gp = 0; gp < 3; gp++) {
#pragma unroll
        for (int k = 0; k < 4; k++)
            prefetch_chunk(&sc, gp * 4 + k, gp * 4 + k, lane, cA, cB, cI);
        cp_commit();
    }
    __syncwarp();                             // ring zeros visible

    for (int g = 0; g < NGROUP; g += 4) {
        // chunk c writes ring slot (c&7)*32; groups alternate base 0/128;
        // mirror store needed only on chunks c % 8 == 0 (k==0 of MIR phases)
        phase< 0,   0, true,  12>(&sc, g + 0, lane, lane_lt7, ring, op, cA, cB, cI);
        phase< 4, 128, false,  0>(&sc, g + 1, lane, lane_lt7, ring, op, cA, cB, cI);
        phase< 8,   0, true,   4>(&sc, g + 2, lane, lane_lt7, ring, op, cA, cB, cI);
        phase<12, 128, false,  8>(&sc, g + 3, lane, lane_lt7, ring, op, cA, cB, cI);
    }
}

// ---------------------------------------------------------------------------
// Inputs (metadata order): f0 [B,N] f32, x [B,N] f32, l_b [B,N,2] f32, K int32
// Output: y [B,N] f32
// ---------------------------------------------------------------------------
extern "C" void kernel_launch(void* const* d_in, const int* in_sizes, int n_in,
                              void* d_out, int out_size)
{
    const float* f0 = (const float*)d_in[0];
    const float* x  = (const float*)d_in[1];
    const float* lb = (const float*)d_in[2];
    float* out = (float*)d_out;

    coef_kernel<<<TOTAL / 256, 256>>>(f0, x, lb);
    lpc_kernel<<<BB, 32>>>(out);
}